// round 2
// baseline (speedup 1.0000x reference)
#include <cuda_runtime.h>
#include <cuda_bf16.h>
#include <math.h>

// Problem constants
#define BATCH 2
#define SEQ   2048
#define CDIM  1024
#define NHEAD 16
#define HDIM  64
#define MROWS (BATCH*SEQ)        // 4096
#define N_QKV (3*CDIM)           // 3072

// Scratch (device globals — allocation-free, referenced directly by kernels)
__device__ float g_qkv[(size_t)MROWS * N_QKV];  // [B*T, 3C]
__device__ float g_y[(size_t)MROWS * CDIM];     // [B*T, C]

// ---------------------------------------------------------------------------
// SGEMM body: C = A[M,K] @ B[K,N], all row-major, M,N mult of 128, K mult of 16
// 128x128 block tile, BK=16, 256 threads, 8x8 per-thread (split 4+4 pattern)
// ---------------------------------------------------------------------------
#define BM 128
#define BN 128
#define BK 16

__device__ __forceinline__ void sgemm_body(
    const float* __restrict__ A, const float* __restrict__ B,
    float* __restrict__ C, int N, int K)
{
    __shared__ float As[BK][BM + 4];   // transposed A tile, padded
    __shared__ float Bs[BK][BN];

    const int tid = threadIdx.x;
    const int tx = tid & 15;           // 0..15
    const int ty = tid >> 4;           // 0..15
    const int brow = blockIdx.y * BM;
    const int bcol = blockIdx.x * BN;

    float acc[8][8];
    #pragma unroll
    for (int i = 0; i < 8; i++)
        #pragma unroll
        for (int j = 0; j < 8; j++) acc[i][j] = 0.f;

    for (int k0 = 0; k0 < K; k0 += BK) {
        // Load A tile: 128 rows x 16 cols = 512 float4; 2 per thread
        #pragma unroll
        for (int i = 0; i < 2; i++) {
            int idx = tid + i * 256;
            int r  = idx >> 2;         // 0..127
            int c4 = idx & 3;          // 0..3
            float4 v = *(const float4*)(A + (size_t)(brow + r) * K + k0 + c4 * 4);
            As[c4*4 + 0][r] = v.x;
            As[c4*4 + 1][r] = v.y;
            As[c4*4 + 2][r] = v.z;
            As[c4*4 + 3][r] = v.w;
        }
        // Load B tile: 16 rows x 128 cols = 512 float4; 2 per thread
        #pragma unroll
        for (int i = 0; i < 2; i++) {
            int idx = tid + i * 256;
            int r  = idx >> 5;         // 0..15
            int c4 = idx & 31;         // 0..31
            *(float4*)(&Bs[r][c4 * 4]) =
                *(const float4*)(B + (size_t)(k0 + r) * N + bcol + c4 * 4);
        }
        __syncthreads();

        #pragma unroll
        for (int k = 0; k < BK; k++) {
            float a[8], bb[8];
            *(float4*)(a)     = *(const float4*)(&As[k][ty * 4]);
            *(float4*)(a + 4) = *(const float4*)(&As[k][64 + ty * 4]);
            *(float4*)(bb)     = *(const float4*)(&Bs[k][tx * 4]);
            *(float4*)(bb + 4) = *(const float4*)(&Bs[k][64 + tx * 4]);
            #pragma unroll
            for (int i = 0; i < 8; i++)
                #pragma unroll
                for (int j = 0; j < 8; j++)
                    acc[i][j] += a[i] * bb[j];
        }
        __syncthreads();
    }

    // Epilogue: rows = brow + {ty*4+i, 64+ty*4+i}, cols = bcol + {tx*4+j, 64+tx*4+j}
    #pragma unroll
    for (int i = 0; i < 8; i++) {
        int r = brow + ((i < 4) ? (ty * 4 + i) : (64 + ty * 4 + (i - 4)));
        float* crow = C + (size_t)r * N + bcol;
        float4 lo = make_float4(acc[i][0], acc[i][1], acc[i][2], acc[i][3]);
        float4 hi = make_float4(acc[i][4], acc[i][5], acc[i][6], acc[i][7]);
        *(float4*)(crow + tx * 4)      = lo;
        *(float4*)(crow + 64 + tx * 4) = hi;
    }
}

// Wrapper kernels: device globals referenced from device code (no
// cudaGetSymbolAddress needed in kernel_launch).
__global__ __launch_bounds__(256) void qkv_gemm_kernel(
    const float* __restrict__ x, const float* __restrict__ Wqkv)
{
    sgemm_body(x, Wqkv, g_qkv, N_QKV, CDIM);
}

__global__ __launch_bounds__(256) void proj_gemm_kernel(
    const float* __restrict__ Wproj, float* __restrict__ out)
{
    sgemm_body(g_y, Wproj, out, CDIM, CDIM);
}

// ---------------------------------------------------------------------------
// Fused causal attention (flash style, fp32).
// One query row per thread, 128 queries per block; K/V tiles of 64 rows in
// shared memory; online softmax in 8-key chunks (registers only).
// grid = (SEQ/128, NHEAD, BATCH), block = 128
// ---------------------------------------------------------------------------
#define FA_BM 128
#define FA_BN 64

__global__ __launch_bounds__(128) void flash_attn_kernel()
{
    __shared__ float Ks[FA_BN * HDIM];
    __shared__ float Vs[FA_BN * HDIM];

    const float* __restrict__ qkv = g_qkv;
    float* __restrict__ y = g_y;

    const int tid = threadIdx.x;
    const int h = blockIdx.y;
    const int b = blockIdx.z;
    const int qi = blockIdx.x * FA_BM + tid;   // global query index in [0,T)

    // Load Q row into registers
    const float* qptr = qkv + ((size_t)(b * SEQ + qi)) * N_QKV + h * HDIM;
    float q[HDIM];
    #pragma unroll
    for (int i = 0; i < HDIM / 4; i++) {
        float4 v = ((const float4*)qptr)[i];
        q[4*i] = v.x; q[4*i+1] = v.y; q[4*i+2] = v.z; q[4*i+3] = v.w;
    }

    float O[HDIM];
    #pragma unroll
    for (int i = 0; i < HDIM; i++) O[i] = 0.f;
    float mrun = -INFINITY, lrun = 0.f;
    const float scale = 0.125f;   // 1/sqrt(64)

    const int ntiles = blockIdx.x * 2 + 2;   // == ((blockIdx.x*128+127)/64)+1
    for (int t = 0; t < ntiles; t++) {
        __syncthreads();   // all threads done reading previous tile
        const int krow0 = t * FA_BN;
        // Cooperative load of K,V tiles: 64 rows x 16 float4 each
        #pragma unroll
        for (int i = 0; i < 8; i++) {
            int idx = tid + i * 128;          // 0..1023
            int r  = idx >> 4;                // 0..63
            int c4 = idx & 15;                // 0..15
            const float* base = qkv + ((size_t)(b * SEQ + krow0 + r)) * N_QKV + h * HDIM;
            ((float4*)Ks)[r * 16 + c4] = ((const float4*)(base + CDIM))[c4];
            ((float4*)Vs)[r * 16 + c4] = ((const float4*)(base + 2 * CDIM))[c4];
        }
        __syncthreads();

        // Process tile in chunks of 8 keys (keeps s[] in registers)
        #pragma unroll 1
        for (int c = 0; c < FA_BN / 8; c++) {
            float s[8];
            float cmax = -INFINITY;
            #pragma unroll
            for (int j = 0; j < 8; j++) {
                const int jj = c * 8 + j;
                const float4* kr = (const float4*)(Ks + jj * HDIM);
                float acc = 0.f;
                #pragma unroll
                for (int i = 0; i < HDIM / 4; i++) {
                    float4 kv = kr[i];
                    acc += kv.x * q[4*i] + kv.y * q[4*i+1]
                         + kv.z * q[4*i+2] + kv.w * q[4*i+3];
                }
                acc *= scale;
                s[j] = (krow0 + jj <= qi) ? acc : -INFINITY;
                cmax = fmaxf(cmax, s[j]);
            }
            if (cmax == -INFINITY) continue;   // whole chunk masked

            const float mnew = fmaxf(mrun, cmax);
            const float corr = __expf(mrun - mnew);  // 0 when mrun == -inf
            lrun *= corr;
            #pragma unroll
            for (int i = 0; i < HDIM; i++) O[i] *= corr;
            mrun = mnew;

            #pragma unroll
            for (int j = 0; j < 8; j++) {
                const float p = __expf(s[j] - mnew);
                lrun += p;
                const float4* vr = (const float4*)(Vs + (c * 8 + j) * HDIM);
                #pragma unroll
                for (int i = 0; i < HDIM / 4; i++) {
                    float4 vv = vr[i];
                    O[4*i]   += p * vv.x;
                    O[4*i+1] += p * vv.y;
                    O[4*i+2] += p * vv.z;
                    O[4*i+3] += p * vv.w;
                }
            }
        }
    }

    // Normalize and write y in [B*T, C] layout (head-major within row)
    const float inv = 1.f / lrun;
    float* yp = y + ((size_t)(b * SEQ + qi)) * CDIM + h * HDIM;
    #pragma unroll
    for (int i = 0; i < HDIM / 4; i++) {
        ((float4*)yp)[i] = make_float4(O[4*i] * inv, O[4*i+1] * inv,
                                       O[4*i+2] * inv, O[4*i+3] * inv);
    }
}

// ---------------------------------------------------------------------------
// Launch — pure kernel launches, nothing else (graph-capture safe).
// ---------------------------------------------------------------------------
extern "C" void kernel_launch(void* const* d_in, const int* in_sizes, int n_in,
                              void* d_out, int out_size)
{
    const float* x     = (const float*)d_in[0];   // [B,T,C]
    const float* Wqkv  = (const float*)d_in[1];   // [C,3C]
    const float* Wproj = (const float*)d_in[2];   // [C,C]
    float* out = (float*)d_out;                   // [B,T,C]

    // 1) qkv = x @ Wqkv   [4096,1024]@[1024,3072]
    {
        dim3 grid(N_QKV / BN, MROWS / BM);
        qkv_gemm_kernel<<<grid, 256>>>(x, Wqkv);
    }
    // 2) fused causal attention -> y [4096,1024]
    {
        dim3 grid(SEQ / FA_BM, NHEAD, BATCH);
        flash_attn_kernel<<<grid, 128>>>();
    }
    // 3) out = y @ Wproj   [4096,1024]@[1024,1024]
    {
        dim3 grid(CDIM / BN, MROWS / BM);
        proj_gemm_kernel<<<grid, 256>>>(Wproj, out);
    }
}

// round 5
// speedup vs baseline: 1.3214x; 1.3214x over previous
#include <cuda_runtime.h>
#include <cuda_bf16.h>
#include <stdint.h>
#include <math.h>

// Problem constants
#define BATCH 2
#define SEQ   2048
#define CDIM  1024
#define NHEAD 16
#define HDIM  64
#define MROWS (BATCH*SEQ)        // 4096
#define N_QKV (3*CDIM)           // 3072

// Scratch (device globals — allocation-free, referenced directly by kernels)
__device__ float g_qkv[(size_t)MROWS * N_QKV];  // [B*T, 3C]
__device__ float g_y[(size_t)MROWS * CDIM];     // [B*T, C]

// ---------------------------------------------------------------------------
// tf32 helpers
// ---------------------------------------------------------------------------
__device__ __forceinline__ uint32_t f2tf32(float x) {
    uint32_t r;
    asm("cvt.rna.tf32.f32 %0, %1;" : "=r"(r) : "f"(x));
    return r;
}

__device__ __forceinline__ void mma_tf32(float* c, const uint32_t* a, const uint32_t* b) {
    asm volatile("mma.sync.aligned.m16n8k8.row.col.f32.tf32.tf32.f32 "
        "{%0,%1,%2,%3}, {%4,%5,%6,%7}, {%8,%9}, {%0,%1,%2,%3};"
        : "+f"(c[0]), "+f"(c[1]), "+f"(c[2]), "+f"(c[3])
        : "r"(a[0]), "r"(a[1]), "r"(a[2]), "r"(a[3]), "r"(b[0]), "r"(b[1]));
}

// ---------------------------------------------------------------------------
// TF32 tensor-core GEMM: C = A[M,K] @ B[K,N], row-major.
// 128x128x32 block tile, 256 threads (8 warps, 2x4), warp tile 64x32,
// m16n8k8 tf32 MMA, fp32 accumulate. M,N mult of 128, K mult of 32.
// ---------------------------------------------------------------------------
#define TBM 128
#define TBN 128
#define TBK 32
#define A_STRIDE 36    // 128 rows x (32+4) pad, conflict-free frag loads
#define B_STRIDE 132   // 32 rows x (128+4) pad, coalesced vector stores

__device__ __forceinline__ void tgemm_body(
    const float* __restrict__ A, const float* __restrict__ B,
    float* __restrict__ C, int N, int K)
{
    __shared__ uint32_t As[TBM * A_STRIDE];   // tf32 bits, row-major
    __shared__ uint32_t Bs[TBK * B_STRIDE];   // tf32 bits, k-major

    const int tid    = threadIdx.x;
    const int lane   = tid & 31;
    const int wid    = tid >> 5;
    const int warp_m = wid & 1;     // 0..1  (64-row slabs)
    const int warp_n = wid >> 1;    // 0..3  (32-col slabs)
    const int brow   = blockIdx.y * TBM;
    const int bcol   = blockIdx.x * TBN;

    const int lq = lane >> 2;   // 0..7
    const int lr = lane & 3;    // 0..3

    float acc[4][4][4];
    #pragma unroll
    for (int mt = 0; mt < 4; mt++)
        #pragma unroll
        for (int nt = 0; nt < 4; nt++)
            #pragma unroll
            for (int i = 0; i < 4; i++) acc[mt][nt][i] = 0.f;

    for (int k0 = 0; k0 < K; k0 += TBK) {
        // Load A tile: 128 rows x 32 cols = 1024 float4; 4 per thread.
        #pragma unroll
        for (int i = 0; i < 4; i++) {
            int idx = tid + i * 256;
            int r  = idx >> 3;          // 0..127
            int c4 = idx & 7;           // 0..7
            float4 v = *(const float4*)(A + (size_t)(brow + r) * K + k0 + c4 * 4);
            uint32_t* dst = &As[r * A_STRIDE + c4 * 4];
            dst[0] = f2tf32(v.x); dst[1] = f2tf32(v.y);
            dst[2] = f2tf32(v.z); dst[3] = f2tf32(v.w);
        }
        // Load B tile: 32 rows x 128 cols = 1024 float4; 4 per thread.
        #pragma unroll
        for (int i = 0; i < 4; i++) {
            int idx = tid + i * 256;
            int r  = idx >> 5;          // 0..31
            int c4 = idx & 31;          // 0..31
            float4 v = *(const float4*)(B + (size_t)(k0 + r) * N + bcol + c4 * 4);
            uint4 t;
            t.x = f2tf32(v.x); t.y = f2tf32(v.y);
            t.z = f2tf32(v.z); t.w = f2tf32(v.w);
            *(uint4*)(&Bs[r * B_STRIDE + c4 * 4]) = t;
        }
        __syncthreads();

        #pragma unroll
        for (int ks = 0; ks < TBK / 8; ks++) {
            const int kk = ks * 8;
            uint32_t a[4][4], b[4][2];
            #pragma unroll
            for (int mt = 0; mt < 4; mt++) {
                const int r = warp_m * 64 + mt * 16 + lq;
                const int cc = kk + lr;
                a[mt][0] = As[r * A_STRIDE + cc];
                a[mt][1] = As[(r + 8) * A_STRIDE + cc];
                a[mt][2] = As[r * A_STRIDE + cc + 4];
                a[mt][3] = As[(r + 8) * A_STRIDE + cc + 4];
            }
            #pragma unroll
            for (int nt = 0; nt < 4; nt++) {
                const int n = warp_n * 32 + nt * 8 + lq;
                b[nt][0] = Bs[(kk + lr) * B_STRIDE + n];
                b[nt][1] = Bs[(kk + lr + 4) * B_STRIDE + n];
            }
            #pragma unroll
            for (int mt = 0; mt < 4; mt++)
                #pragma unroll
                for (int nt = 0; nt < 4; nt++)
                    mma_tf32(acc[mt][nt], a[mt], b[nt]);
        }
        __syncthreads();
    }

    // Epilogue: per fragment, thread holds (row,col), (row,col+1), (row+8, ...).
    #pragma unroll
    for (int mt = 0; mt < 4; mt++) {
        const int row0 = brow + warp_m * 64 + mt * 16 + lq;
        #pragma unroll
        for (int nt = 0; nt < 4; nt++) {
            const int col = bcol + warp_n * 32 + nt * 8 + 2 * lr;
            *(float2*)(C + (size_t)row0 * N + col) =
                make_float2(acc[mt][nt][0], acc[mt][nt][1]);
            *(float2*)(C + (size_t)(row0 + 8) * N + col) =
                make_float2(acc[mt][nt][2], acc[mt][nt][3]);
        }
    }
}

__global__ __launch_bounds__(256) void qkv_gemm_kernel(
    const float* __restrict__ x, const float* __restrict__ Wqkv)
{
    tgemm_body(x, Wqkv, g_qkv, N_QKV, CDIM);
}

__global__ __launch_bounds__(256) void proj_gemm_kernel(
    const float* __restrict__ Wproj, float* __restrict__ out)
{
    tgemm_body(g_y, Wproj, out, CDIM, CDIM);
}

// ---------------------------------------------------------------------------
// Fused causal attention (flash style, fp32) — unchanged from R2.
// grid = (SEQ/128, NHEAD, BATCH), block = 128
// ---------------------------------------------------------------------------
#define FA_BM 128
#define FA_BN 64

__global__ __launch_bounds__(128) void flash_attn_kernel()
{
    __shared__ float Ks[FA_BN * HDIM];
    __shared__ float Vs[FA_BN * HDIM];

    const float* __restrict__ qkv = g_qkv;
    float* __restrict__ y = g_y;

    const int tid = threadIdx.x;
    const int h = blockIdx.y;
    const int b = blockIdx.z;
    const int qi = blockIdx.x * FA_BM + tid;   // global query index in [0,T)

    const float* qptr = qkv + ((size_t)(b * SEQ + qi)) * N_QKV + h * HDIM;
    float q[HDIM];
    #pragma unroll
    for (int i = 0; i < HDIM / 4; i++) {
        float4 v = ((const float4*)qptr)[i];
        q[4*i] = v.x; q[4*i+1] = v.y; q[4*i+2] = v.z; q[4*i+3] = v.w;
    }

    float O[HDIM];
    #pragma unroll
    for (int i = 0; i < HDIM; i++) O[i] = 0.f;
    float mrun = -INFINITY, lrun = 0.f;
    const float scale = 0.125f;   // 1/sqrt(64)

    const int ntiles = blockIdx.x * 2 + 2;
    for (int t = 0; t < ntiles; t++) {
        __syncthreads();
        const int krow0 = t * FA_BN;
        #pragma unroll
        for (int i = 0; i < 8; i++) {
            int idx = tid + i * 128;
            int r  = idx >> 4;
            int c4 = idx & 15;
            const float* base = qkv + ((size_t)(b * SEQ + krow0 + r)) * N_QKV + h * HDIM;
            ((float4*)Ks)[r * 16 + c4] = ((const float4*)(base + CDIM))[c4];
            ((float4*)Vs)[r * 16 + c4] = ((const float4*)(base + 2 * CDIM))[c4];
        }
        __syncthreads();

        #pragma unroll 1
        for (int c = 0; c < FA_BN / 8; c++) {
            float s[8];
            float cmax = -INFINITY;
            #pragma unroll
            for (int j = 0; j < 8; j++) {
                const int jj = c * 8 + j;
                const float4* kr = (const float4*)(Ks + jj * HDIM);
                float acc = 0.f;
                #pragma unroll
                for (int i = 0; i < HDIM / 4; i++) {
                    float4 kv = kr[i];
                    acc += kv.x * q[4*i] + kv.y * q[4*i+1]
                         + kv.z * q[4*i+2] + kv.w * q[4*i+3];
                }
                acc *= scale;
                s[j] = (krow0 + jj <= qi) ? acc : -INFINITY;
                cmax = fmaxf(cmax, s[j]);
            }
            if (cmax == -INFINITY) continue;

            const float mnew = fmaxf(mrun, cmax);
            const float corr = __expf(mrun - mnew);
            lrun *= corr;
            #pragma unroll
            for (int i = 0; i < HDIM; i++) O[i] *= corr;
            mrun = mnew;

            #pragma unroll
            for (int j = 0; j < 8; j++) {
                const float p = __expf(s[j] - mnew);
                lrun += p;
                const float4* vr = (const float4*)(Vs + (c * 8 + j) * HDIM);
                #pragma unroll
                for (int i = 0; i < HDIM / 4; i++) {
                    float4 vv = vr[i];
                    O[4*i]   += p * vv.x;
                    O[4*i+1] += p * vv.y;
                    O[4*i+2] += p * vv.z;
                    O[4*i+3] += p * vv.w;
                }
            }
        }
    }

    const float inv = 1.f / lrun;
    float* yp = y + ((size_t)(b * SEQ + qi)) * CDIM + h * HDIM;
    #pragma unroll
    for (int i = 0; i < HDIM / 4; i++) {
        ((float4*)yp)[i] = make_float4(O[4*i] * inv, O[4*i+1] * inv,
                                       O[4*i+2] * inv, O[4*i+3] * inv);
    }
}

// ---------------------------------------------------------------------------
// Launch — pure kernel launches (graph-capture safe).
// ---------------------------------------------------------------------------
extern "C" void kernel_launch(void* const* d_in, const int* in_sizes, int n_in,
                              void* d_out, int out_size)
{
    const float* x     = (const float*)d_in[0];   // [B,T,C]
    const float* Wqkv  = (const float*)d_in[1];   // [C,3C]
    const float* Wproj = (const float*)d_in[2];   // [C,C]
    float* out = (float*)d_out;                   // [B,T,C]

    {   // 1) qkv = x @ Wqkv   [4096,1024]@[1024,3072]
        dim3 grid(N_QKV / TBN, MROWS / TBM);
        qkv_gemm_kernel<<<grid, 256>>>(x, Wqkv);
    }
    {   // 2) fused causal attention -> y [4096,1024]
        dim3 grid(SEQ / FA_BM, NHEAD, BATCH);
        flash_attn_kernel<<<grid, 128>>>();
    }
    {   // 3) out = y @ Wproj   [4096,1024]@[1024,1024]
        dim3 grid(CDIM / TBN, MROWS / TBM);
        proj_gemm_kernel<<<grid, 256>>>(Wproj, out);
    }
}

// round 6
// speedup vs baseline: 3.1853x; 2.4106x over previous
#include <cuda_runtime.h>
#include <cuda_bf16.h>
#include <stdint.h>
#include <math.h>

// Problem constants
#define BATCH 2
#define SEQ   2048
#define CDIM  1024
#define NHEAD 16
#define HDIM  64
#define MROWS (BATCH*SEQ)        // 4096
#define N_QKV (3*CDIM)           // 3072

// Scratch (device globals — allocation-free, referenced directly by kernels)
__device__ float g_qkv[(size_t)MROWS * N_QKV];  // [B*T, 3C]
__device__ float g_y[(size_t)MROWS * CDIM];     // [B*T, C]

// ---------------------------------------------------------------------------
// tf32 helpers
// ---------------------------------------------------------------------------
__device__ __forceinline__ uint32_t f2tf32(float x) {
    uint32_t r;
    asm("cvt.rna.tf32.f32 %0, %1;" : "=r"(r) : "f"(x));
    return r;
}

__device__ __forceinline__ void mma_tf32(float* c, const uint32_t* a, const uint32_t* b) {
    asm volatile("mma.sync.aligned.m16n8k8.row.col.f32.tf32.tf32.f32 "
        "{%0,%1,%2,%3}, {%4,%5,%6,%7}, {%8,%9}, {%0,%1,%2,%3};"
        : "+f"(c[0]), "+f"(c[1]), "+f"(c[2]), "+f"(c[3])
        : "r"(a[0]), "r"(a[1]), "r"(a[2]), "r"(a[3]), "r"(b[0]), "r"(b[1]));
}

// ---------------------------------------------------------------------------
// TF32 tensor-core GEMM (unchanged from R5): C = A[M,K] @ B[K,N], row-major.
// ---------------------------------------------------------------------------
#define TBM 128
#define TBN 128
#define TBK 32
#define A_STRIDE 36
#define B_STRIDE 132

__device__ __forceinline__ void tgemm_body(
    const float* __restrict__ A, const float* __restrict__ B,
    float* __restrict__ C, int N, int K)
{
    __shared__ uint32_t As[TBM * A_STRIDE];
    __shared__ uint32_t Bs[TBK * B_STRIDE];

    const int tid    = threadIdx.x;
    const int lane   = tid & 31;
    const int wid    = tid >> 5;
    const int warp_m = wid & 1;
    const int warp_n = wid >> 1;
    const int brow   = blockIdx.y * TBM;
    const int bcol   = blockIdx.x * TBN;

    const int lq = lane >> 2;
    const int lr = lane & 3;

    float acc[4][4][4];
    #pragma unroll
    for (int mt = 0; mt < 4; mt++)
        #pragma unroll
        for (int nt = 0; nt < 4; nt++)
            #pragma unroll
            for (int i = 0; i < 4; i++) acc[mt][nt][i] = 0.f;

    for (int k0 = 0; k0 < K; k0 += TBK) {
        #pragma unroll
        for (int i = 0; i < 4; i++) {
            int idx = tid + i * 256;
            int r  = idx >> 3;
            int c4 = idx & 7;
            float4 v = *(const float4*)(A + (size_t)(brow + r) * K + k0 + c4 * 4);
            uint32_t* dst = &As[r * A_STRIDE + c4 * 4];
            dst[0] = f2tf32(v.x); dst[1] = f2tf32(v.y);
            dst[2] = f2tf32(v.z); dst[3] = f2tf32(v.w);
        }
        #pragma unroll
        for (int i = 0; i < 4; i++) {
            int idx = tid + i * 256;
            int r  = idx >> 5;
            int c4 = idx & 31;
            float4 v = *(const float4*)(B + (size_t)(k0 + r) * N + bcol + c4 * 4);
            uint4 t;
            t.x = f2tf32(v.x); t.y = f2tf32(v.y);
            t.z = f2tf32(v.z); t.w = f2tf32(v.w);
            *(uint4*)(&Bs[r * B_STRIDE + c4 * 4]) = t;
        }
        __syncthreads();

        #pragma unroll
        for (int ks = 0; ks < TBK / 8; ks++) {
            const int kk = ks * 8;
            uint32_t a[4][4], b[4][2];
            #pragma unroll
            for (int mt = 0; mt < 4; mt++) {
                const int r = warp_m * 64 + mt * 16 + lq;
                const int cc = kk + lr;
                a[mt][0] = As[r * A_STRIDE + cc];
                a[mt][1] = As[(r + 8) * A_STRIDE + cc];
                a[mt][2] = As[r * A_STRIDE + cc + 4];
                a[mt][3] = As[(r + 8) * A_STRIDE + cc + 4];
            }
            #pragma unroll
            for (int nt = 0; nt < 4; nt++) {
                const int n = warp_n * 32 + nt * 8 + lq;
                b[nt][0] = Bs[(kk + lr) * B_STRIDE + n];
                b[nt][1] = Bs[(kk + lr + 4) * B_STRIDE + n];
            }
            #pragma unroll
            for (int mt = 0; mt < 4; mt++)
                #pragma unroll
                for (int nt = 0; nt < 4; nt++)
                    mma_tf32(acc[mt][nt], a[mt], b[nt]);
        }
        __syncthreads();
    }

    #pragma unroll
    for (int mt = 0; mt < 4; mt++) {
        const int row0 = brow + warp_m * 64 + mt * 16 + lq;
        #pragma unroll
        for (int nt = 0; nt < 4; nt++) {
            const int col = bcol + warp_n * 32 + nt * 8 + 2 * lr;
            *(float2*)(C + (size_t)row0 * N + col) =
                make_float2(acc[mt][nt][0], acc[mt][nt][1]);
            *(float2*)(C + (size_t)(row0 + 8) * N + col) =
                make_float2(acc[mt][nt][2], acc[mt][nt][3]);
        }
    }
}

__global__ __launch_bounds__(256) void qkv_gemm_kernel(
    const float* __restrict__ x, const float* __restrict__ Wqkv)
{
    tgemm_body(x, Wqkv, g_qkv, N_QKV, CDIM);
}

__global__ __launch_bounds__(256) void proj_gemm_kernel(
    const float* __restrict__ Wproj, float* __restrict__ out)
{
    tgemm_body(g_y, Wproj, out, CDIM, CDIM);
}

// ---------------------------------------------------------------------------
// Tensor-core fused causal flash attention (tf32 m16n8k8).
// Block: 256 threads = 8 warps; each warp owns 16 query rows (block = 128 q).
// KV tile = 64 keys. K/V staged as tf32 in smem, stride 72 (conflict-free for
// both the K b-frag pattern 8*lq+lr and the V b-frag pattern 8*lr+lq).
// P C-fragments are converted to A-fragments with shfl (no smem round-trip).
// grid = (SEQ/128, NHEAD, BATCH)
// ---------------------------------------------------------------------------
#define FA_Q 128
#define FA_K 64
#define FA_ST 72

__global__ __launch_bounds__(256) void flash_attn_tc_kernel()
{
    __shared__ uint32_t KVs[2 * FA_K * FA_ST];   // K tile | V tile; Q staging at start
    uint32_t* Ks = KVs;
    uint32_t* Vs = KVs + FA_K * FA_ST;

    const float* __restrict__ qkv = g_qkv;
    float* __restrict__ y = g_y;

    const int tid  = threadIdx.x;
    const int lane = tid & 31;
    const int w    = tid >> 5;          // warp 0..7
    const int lq   = lane >> 2;         // 0..7
    const int lr   = lane & 3;          // 0..3
    const int h    = blockIdx.y;
    const int b    = blockIdx.z;
    const int q0   = blockIdx.x * FA_Q;
    const size_t rowbase = (size_t)b * SEQ;
    const float scale = 0.125f;         // 1/sqrt(64)

    // ---- Stage Q tile (128 x 64) into KVs (exact size match), grab A-frags
    #pragma unroll
    for (int i = 0; i < 8; i++) {
        int idx = tid + i * 256;        // 0..2047 float4 slots
        int r  = idx >> 4;              // 0..127
        int c4 = idx & 15;              // 0..15
        float4 v = *(const float4*)(qkv + (rowbase + q0 + r) * N_QKV + h * HDIM + c4 * 4);
        uint4 t;
        t.x = f2tf32(v.x); t.y = f2tf32(v.y);
        t.z = f2tf32(v.z); t.w = f2tf32(v.w);
        *(uint4*)&KVs[r * FA_ST + c4 * 4] = t;
    }
    __syncthreads();

    uint32_t qf[8][4];                  // Q A-fragments, full HD=64
    {
        const int r0 = (w * 16 + lq) * FA_ST;
        const int r1 = (w * 16 + lq + 8) * FA_ST;
        #pragma unroll
        for (int ks = 0; ks < 8; ks++) {
            const int kk = ks * 8;
            qf[ks][0] = KVs[r0 + kk + lr];
            qf[ks][1] = KVs[r1 + kk + lr];
            qf[ks][2] = KVs[r0 + kk + lr + 4];
            qf[ks][3] = KVs[r1 + kk + lr + 4];
        }
    }

    float o[8][4];
    #pragma unroll
    for (int nt = 0; nt < 8; nt++)
        #pragma unroll
        for (int i = 0; i < 4; i++) o[nt][i] = 0.f;
    float m0 = -INFINITY, m1 = -INFINITY, l0 = 0.f, l1 = 0.f;

    const int row0 = q0 + w * 16 + lq;  // this thread's first query row
    const int row1 = row0 + 8;
    const int wrow_max = q0 + w * 16 + 15;
    const int ntiles = 2 * blockIdx.x + 2;

    for (int t = 0; t < ntiles; t++) {
        const int krow0 = t * FA_K;
        __syncthreads();                 // protect smem reuse from previous iter
        // ---- cooperative K,V tile load (64 x 64 each)
        #pragma unroll
        for (int i = 0; i < 4; i++) {
            int idx = tid + i * 256;     // 0..1023
            int r  = idx >> 4;           // 0..63
            int c4 = idx & 15;
            const float* base = qkv + (rowbase + krow0 + r) * N_QKV + h * HDIM;
            float4 kv = *(const float4*)(base + CDIM + c4 * 4);
            float4 vv = *(const float4*)(base + 2 * CDIM + c4 * 4);
            uint4 tk, tv;
            tk.x = f2tf32(kv.x); tk.y = f2tf32(kv.y);
            tk.z = f2tf32(kv.z); tk.w = f2tf32(kv.w);
            tv.x = f2tf32(vv.x); tv.y = f2tf32(vv.y);
            tv.z = f2tf32(vv.z); tv.w = f2tf32(vv.w);
            *(uint4*)&Ks[r * FA_ST + c4 * 4] = tk;
            *(uint4*)&Vs[r * FA_ST + c4 * 4] = tv;
        }
        __syncthreads();

        if (krow0 > wrow_max) continue;  // warp-uniform: whole warp tile masked

        // ---- S = Q K^T  (16 x 64), 8 n-tiles x 8 k-steps
        float s[8][4];
        #pragma unroll
        for (int nt = 0; nt < 8; nt++)
            #pragma unroll
            for (int i = 0; i < 4; i++) s[nt][i] = 0.f;

        #pragma unroll
        for (int ks = 0; ks < 8; ks++) {
            const int kk = ks * 8;
            #pragma unroll
            for (int nt = 0; nt < 8; nt++) {
                uint32_t bb[2];
                bb[0] = Ks[(nt * 8 + lq) * FA_ST + kk + lr];
                bb[1] = Ks[(nt * 8 + lq) * FA_ST + kk + lr + 4];
                mma_tf32(s[nt], qf[ks], bb);
            }
        }

        // ---- scale + causal mask
        const bool diag = (krow0 + FA_K - 1 > q0 + w * 16);
        #pragma unroll
        for (int nt = 0; nt < 8; nt++) {
            const int col = krow0 + nt * 8 + 2 * lr;
            s[nt][0] = (diag && col     > row0) ? -INFINITY : s[nt][0] * scale;
            s[nt][1] = (diag && col + 1 > row0) ? -INFINITY : s[nt][1] * scale;
            s[nt][2] = (diag && col     > row1) ? -INFINITY : s[nt][2] * scale;
            s[nt][3] = (diag && col + 1 > row1) ? -INFINITY : s[nt][3] * scale;
        }

        // ---- online softmax (rows lq and lq+8)
        float mx0 = -INFINITY, mx1 = -INFINITY;
        #pragma unroll
        for (int nt = 0; nt < 8; nt++) {
            mx0 = fmaxf(mx0, fmaxf(s[nt][0], s[nt][1]));
            mx1 = fmaxf(mx1, fmaxf(s[nt][2], s[nt][3]));
        }
        mx0 = fmaxf(mx0, __shfl_xor_sync(0xffffffffu, mx0, 1));
        mx0 = fmaxf(mx0, __shfl_xor_sync(0xffffffffu, mx0, 2));
        mx1 = fmaxf(mx1, __shfl_xor_sync(0xffffffffu, mx1, 1));
        mx1 = fmaxf(mx1, __shfl_xor_sync(0xffffffffu, mx1, 2));

        const float mn0 = fmaxf(m0, mx0);
        const float mn1 = fmaxf(m1, mx1);
        const float cr0 = __expf(m0 - mn0);
        const float cr1 = __expf(m1 - mn1);
        m0 = mn0; m1 = mn1;

        float sum0 = 0.f, sum1 = 0.f;
        #pragma unroll
        for (int nt = 0; nt < 8; nt++) {
            s[nt][0] = __expf(s[nt][0] - mn0); sum0 += s[nt][0];
            s[nt][1] = __expf(s[nt][1] - mn0); sum0 += s[nt][1];
            s[nt][2] = __expf(s[nt][2] - mn1); sum1 += s[nt][2];
            s[nt][3] = __expf(s[nt][3] - mn1); sum1 += s[nt][3];
        }
        sum0 += __shfl_xor_sync(0xffffffffu, sum0, 1);
        sum0 += __shfl_xor_sync(0xffffffffu, sum0, 2);
        sum1 += __shfl_xor_sync(0xffffffffu, sum1, 1);
        sum1 += __shfl_xor_sync(0xffffffffu, sum1, 2);
        l0 = l0 * cr0 + sum0;
        l1 = l1 * cr1 + sum1;

        #pragma unroll
        for (int nt = 0; nt < 8; nt++) {
            o[nt][0] *= cr0; o[nt][1] *= cr0;
            o[nt][2] *= cr1; o[nt][3] *= cr1;
        }

        // ---- O += P V : convert P C-frags -> A-frags via shfl, then mma
        const int srcl = (lane & ~3) | (lr >> 1);
        const int srch = srcl + 2;
        const bool odd = (lr & 1);
        #pragma unroll
        for (int kc = 0; kc < 8; kc++) {
            const float c0 = s[kc][0], c1 = s[kc][1];
            const float c2 = s[kc][2], c3 = s[kc][3];
            const float t00 = __shfl_sync(0xffffffffu, c0, srcl);
            const float t01 = __shfl_sync(0xffffffffu, c1, srcl);
            const float t10 = __shfl_sync(0xffffffffu, c2, srcl);
            const float t11 = __shfl_sync(0xffffffffu, c3, srcl);
            const float u00 = __shfl_sync(0xffffffffu, c0, srch);
            const float u01 = __shfl_sync(0xffffffffu, c1, srch);
            const float u10 = __shfl_sync(0xffffffffu, c2, srch);
            const float u11 = __shfl_sync(0xffffffffu, c3, srch);
            uint32_t a[4];
            a[0] = f2tf32(odd ? t01 : t00);
            a[1] = f2tf32(odd ? t11 : t10);
            a[2] = f2tf32(odd ? u01 : u00);
            a[3] = f2tf32(odd ? u11 : u10);
            #pragma unroll
            for (int nt = 0; nt < 8; nt++) {
                uint32_t bb[2];
                bb[0] = Vs[(kc * 8 + lr) * FA_ST + nt * 8 + lq];
                bb[1] = Vs[(kc * 8 + lr + 4) * FA_ST + nt * 8 + lq];
                mma_tf32(o[nt], a, bb);
            }
        }
    }

    // ---- epilogue: normalize, write y[B*T, C] (head-major slice)
    const float inv0 = 1.f / l0;
    const float inv1 = 1.f / l1;
    #pragma unroll
    for (int nt = 0; nt < 8; nt++) {
        const int col = h * HDIM + nt * 8 + 2 * lr;
        *(float2*)(y + (rowbase + row0) * CDIM + col) =
            make_float2(o[nt][0] * inv0, o[nt][1] * inv0);
        *(float2*)(y + (rowbase + row1) * CDIM + col) =
            make_float2(o[nt][2] * inv1, o[nt][3] * inv1);
    }
}

// ---------------------------------------------------------------------------
// Launch — pure kernel launches (graph-capture safe).
// ---------------------------------------------------------------------------
extern "C" void kernel_launch(void* const* d_in, const int* in_sizes, int n_in,
                              void* d_out, int out_size)
{
    const float* x     = (const float*)d_in[0];   // [B,T,C]
    const float* Wqkv  = (const float*)d_in[1];   // [C,3C]
    const float* Wproj = (const float*)d_in[2];   // [C,C]
    float* out = (float*)d_out;                   // [B,T,C]

    {   // 1) qkv = x @ Wqkv
        dim3 grid(N_QKV / TBN, MROWS / TBM);
        qkv_gemm_kernel<<<grid, 256>>>(x, Wqkv);
    }
    {   // 2) fused causal attention -> y
        dim3 grid(SEQ / FA_Q, NHEAD, BATCH);
        flash_attn_tc_kernel<<<grid, 256>>>();
    }
    {   // 3) out = y @ Wproj
        dim3 grid(CDIM / TBN, MROWS / TBM);
        proj_gemm_kernel<<<grid, 256>>>(Wproj, out);
    }
}